// round 11
// baseline (speedup 1.0000x reference)
#include <cuda_runtime.h>

#define BATCH 32
#define HW 307200            // 480*640
#define HW4 (HW/4)           // 76800 float4 per channel per batch
#define GRID 888             // 148 SMs * 6 blocks, all co-resident
#define NGROUP 4             // batch groups
#define GBATCH 8             // batches per group
#define P2B 111              // blocks per batch (111*8 = 888)
#define CHUNK 692            // ceil(76800/111) float4 positions per block

__device__ float g_partial[BATCH * P2B];
__device__ volatile unsigned int g_arrive;

__device__ __forceinline__ void grid_sync()
{
    __syncthreads();
    if (threadIdx.x == 0) {
        __threadfence();
        unsigned int old = atomicAdd((unsigned int*)&g_arrive, 1u);
        unsigned int target = (old / GRID + 1u) * GRID;
        while (g_arrive < target) { __nanosleep(64); }
        __threadfence();
    }
    __syncthreads();
}

// Branchless hue: out_n = v - cr * sat(min(k, 4-k)), k = (n + 6h) mod 6, n={5,3,1}.
__device__ __forceinline__ void px_proc(float r, float g, float bl,
                                        float bf, float cf, float cmean,
                                        float sf, float hf,
                                        float& ro, float& go, float& bo)
{
    r  = __saturatef(r * bf);
    g  = __saturatef(g * bf);
    bl = __saturatef(bl * bf);
    r  = __saturatef(fmaf(cf, r,  cmean));
    g  = __saturatef(fmaf(cf, g,  cmean));
    bl = __saturatef(fmaf(cf, bl, cmean));
    float gray = 0.299f * r + 0.587f * g + 0.114f * bl;
    float gm = (1.0f - sf) * gray;
    r  = __saturatef(fmaf(sf, r,  gm));
    g  = __saturatef(fmaf(sf, g,  gm));
    bl = __saturatef(fmaf(sf, bl, gm));
    float maxc = fmaxf(r, fmaxf(g, bl));
    float minc = fminf(r, fminf(g, bl));
    float cr = maxc - minc;
    float crd = (cr == 0.0f) ? 1.0f : cr;
    float inv = __fdividef(1.0f, crd);
    float num, off;
    if (maxc == r)      { num = g - bl;  off = 0.0f; }
    else if (maxc == g) { num = bl - r;  off = 2.0f; }
    else                { num = r - g;   off = 4.0f; }
    float h6r = fmaf(num, inv, off);
    float hh = fmaf(h6r, 0.166666672f, hf);
    hh = hh - floorf(hh);
    float h6 = hh * 6.0f;
    float kr = 5.0f + h6; kr = (kr >= 6.0f) ? kr - 6.0f : kr;
    float kg = 3.0f + h6; kg = (kg >= 6.0f) ? kg - 6.0f : kg;
    float kb = 1.0f + h6; kb = (kb >= 6.0f) ? kb - 6.0f : kb;
    float wr = __saturatef(fminf(kr, 4.0f - kr));
    float wg = __saturatef(fminf(kg, 4.0f - kg));
    float wb = __saturatef(fminf(kb, 4.0f - kb));
    ro = fmaf(-wr, cr, maxc);
    go = fmaf(-wg, cr, maxc);
    bo = fmaf(-wb, cr, maxc);
}

__global__ void __launch_bounds__(256, 6)
cr_smem_kernel(const float* __restrict__ x,
               const float* __restrict__ bf_arr,
               const float* __restrict__ cf_arr,
               const float* __restrict__ sf_arr,
               const float* __restrict__ hf_arr,
               float* __restrict__ out)
{
    __shared__ float4 tile[3 * CHUNK];   // 33216 B: this block's chunk, all 3 channels
    __shared__ float sm[5];

    int b_local = blockIdx.x / P2B;     // 0..7
    int sub     = blockIdx.x % P2B;     // 0..110
    int start4  = sub * CHUNK;
    int end4    = min(start4 + CHUNK, HW4);
    int lane = threadIdx.x & 31, wid = threadIdx.x >> 5;

    for (int grp = 0; grp < NGROUP; grp++) {
        int b = grp * GBATCH + b_local;
        size_t base = (size_t)b * 3 * HW;
        const float4* px = (const float4*)(x + base);
        float bf = bf_arr[b];

        // -------- Phase 1: load chunk -> smem, partial gray sum of clip(x*bf) --------
        float acc = 0.0f;
        for (int i = start4 + threadIdx.x; i < end4; i += 256) {
            int j = i - start4;
            float4 r  = px[i];
            float4 g  = px[i + HW4];
            float4 bl = px[i + 2 * HW4];
            tile[j]             = r;
            tile[j + CHUNK]     = g;
            tile[j + 2 * CHUNK] = bl;
            float rr = __saturatef(r.x * bf) + __saturatef(r.y * bf)
                     + __saturatef(r.z * bf) + __saturatef(r.w * bf);
            float gg = __saturatef(g.x * bf) + __saturatef(g.y * bf)
                     + __saturatef(g.z * bf) + __saturatef(g.w * bf);
            float bb = __saturatef(bl.x * bf) + __saturatef(bl.y * bf)
                     + __saturatef(bl.z * bf) + __saturatef(bl.w * bf);
            acc += 0.299f * rr + 0.587f * gg + 0.114f * bb;
        }
        // block-reduce acc (warp shuffle + tiny smem)
        #pragma unroll
        for (int off = 16; off > 0; off >>= 1)
            acc += __shfl_down_sync(0xFFFFFFFFu, acc, off);
        __shared__ float sw[8];
        if (lane == 0) sw[wid] = acc;
        __syncthreads();
        if (wid == 0) {
            float v = (lane < 8) ? sw[lane] : 0.0f;
            #pragma unroll
            for (int off = 4; off > 0; off >>= 1)
                v += __shfl_down_sync(0xFFFFFFFFu, v, off);
            if (lane == 0) g_partial[b * P2B + sub] = v;
        }

        // -------- Grid barrier: all partials of this group's batches visible --------
        grid_sync();

        // -------- Sum 111 partials for this block's batch (one warp, fixed order) ----
        if (wid == 0) {
            float v = 0.0f;
            for (int i = lane; i < P2B; i += 32) v += g_partial[b * P2B + i];
            #pragma unroll
            for (int off = 16; off > 0; off >>= 1)
                v += __shfl_down_sync(0xFFFFFFFFu, v, off);
            if (lane == 0) {
                float mean = v * (1.0f / (float)HW);
                float cf = cf_arr[b];
                sm[0] = (1.0f - cf) * mean;   // cmean
                sm[1] = cf;
                sm[2] = sf_arr[b];
                sm[3] = hf_arr[b];
            }
        }
        __syncthreads();
        float cmean = sm[0], cf = sm[1], sf = sm[2], hf = sm[3];

        // -------- Phase 2: process from SMEM (no global re-read), write out --------
        float4* pox = (float4*)(out + base);
        for (int i = start4 + threadIdx.x; i < end4; i += 256) {
            int j = i - start4;
            float4 R  = tile[j];
            float4 G  = tile[j + CHUNK];
            float4 Bv = tile[j + 2 * CHUNK];
            float4 Ro, Go, Bo;
            px_proc(R.x, G.x, Bv.x, bf, cf, cmean, sf, hf, Ro.x, Go.x, Bo.x);
            px_proc(R.y, G.y, Bv.y, bf, cf, cmean, sf, hf, Ro.y, Go.y, Bo.y);
            px_proc(R.z, G.z, Bv.z, bf, cf, cmean, sf, hf, Ro.z, Go.z, Bo.z);
            px_proc(R.w, G.w, Bv.w, bf, cf, cmean, sf, hf, Ro.w, Go.w, Bo.w);
            pox[i]           = Ro;
            pox[i + HW4]     = Go;
            pox[i + 2 * HW4] = Bo;
        }
        __syncthreads();   // tile/sm reuse safety before next group
    }
}

extern "C" void kernel_launch(void* const* d_in, const int* in_sizes, int n_in,
                              void* d_out, int out_size)
{
    const float* x  = (const float*)d_in[0];
    const float* bf = (const float*)d_in[1];
    const float* cf = (const float*)d_in[2];
    const float* sf = (const float*)d_in[3];
    const float* hf = (const float*)d_in[4];
    float* out = (float*)d_out;

    // Ensure max SMEM carveout so 6 blocks/SM residency holds (barrier safety).
    cudaFuncSetAttribute(cr_smem_kernel,
                         cudaFuncAttributePreferredSharedMemoryCarveout, 100);

    cr_smem_kernel<<<GRID, 256>>>(x, bf, cf, sf, hf, out);
}

// round 12
// speedup vs baseline: 1.2388x; 1.2388x over previous
#include <cuda_runtime.h>

#define BATCH 32
#define HW 307200            // 480*640
#define HW4 (HW/4)           // 76800 float4 per channel per batch
#define NBLK 75              // reduction blocks per batch -> 2400 total
#define CHUNK4 1024          // 76800/75 ; 4 iters/thread exactly
#define BLKS_PER_BATCH 150   // HW4 / (256*2) : 2 float4 triplets per thread

__device__ float g_partial[BATCH * NBLK];

// ---------------- Pass 1: per-batch gray sum of clip(x*bf) ----------------
__global__ void __launch_bounds__(256)
cr_reduce_kernel(const float* __restrict__ x, const float* __restrict__ bf_arr)
{
    int blk = blockIdx.x;          // 0 .. BATCH*NBLK-1
    int b   = blk / NBLK;
    int sub = blk % NBLK;
    float bf = bf_arr[b];

    const float4* base = (const float4*)(x + (size_t)b * 3 * HW);
    int start4 = sub * CHUNK4 + threadIdx.x;

    float acc = 0.0f;
    #pragma unroll
    for (int it = 0; it < 4; it++) {
        int p4 = start4 + it * 256;
        float4 r  = base[p4];
        float4 g  = base[p4 + HW4];
        float4 bl = base[p4 + 2 * HW4];
        float rr = __saturatef(r.x * bf) + __saturatef(r.y * bf)
                 + __saturatef(r.z * bf) + __saturatef(r.w * bf);
        float gg = __saturatef(g.x * bf) + __saturatef(g.y * bf)
                 + __saturatef(g.z * bf) + __saturatef(g.w * bf);
        float bb = __saturatef(bl.x * bf) + __saturatef(bl.y * bf)
                 + __saturatef(bl.z * bf) + __saturatef(bl.w * bf);
        acc += 0.299f * rr + 0.587f * gg + 0.114f * bb;
    }

    // warp reduce
    #pragma unroll
    for (int off = 16; off > 0; off >>= 1)
        acc += __shfl_down_sync(0xFFFFFFFFu, acc, off);

    __shared__ float s[8];
    int lane = threadIdx.x & 31, wid = threadIdx.x >> 5;
    if (lane == 0) s[wid] = acc;
    __syncthreads();
    if (wid == 0) {
        float v = (lane < 8) ? s[lane] : 0.0f;
        #pragma unroll
        for (int off = 4; off > 0; off >>= 1)
            v += __shfl_down_sync(0xFFFFFFFFu, v, off);
        if (lane == 0) g_partial[blk] = v;
    }
}

// ---------------- Pass 2: fused brightness/contrast/saturation/hue ----------------
// Branchless hue: out_n = v - cr * sat(min(k, 4-k)), k = (n + 6h) mod 6, n={5,3,1}.
__device__ __forceinline__ void px_proc(float r, float g, float bl,
                                        float bf, float cf, float cmean,
                                        float sf, float hf,
                                        float& ro, float& go, float& bo)
{
    r  = __saturatef(r * bf);
    g  = __saturatef(g * bf);
    bl = __saturatef(bl * bf);
    r  = __saturatef(fmaf(cf, r,  cmean));
    g  = __saturatef(fmaf(cf, g,  cmean));
    bl = __saturatef(fmaf(cf, bl, cmean));
    float gray = 0.299f * r + 0.587f * g + 0.114f * bl;
    float gm = (1.0f - sf) * gray;
    r  = __saturatef(fmaf(sf, r,  gm));
    g  = __saturatef(fmaf(sf, g,  gm));
    bl = __saturatef(fmaf(sf, bl, gm));
    float maxc = fmaxf(r, fmaxf(g, bl));
    float minc = fminf(r, fminf(g, bl));
    float cr = maxc - minc;
    float crd = (cr == 0.0f) ? 1.0f : cr;
    float inv = __fdividef(1.0f, crd);
    float num, off;
    if (maxc == r)      { num = g - bl;  off = 0.0f; }
    else if (maxc == g) { num = bl - r;  off = 2.0f; }
    else                { num = r - g;   off = 4.0f; }
    float h6r = fmaf(num, inv, off);
    float hh = fmaf(h6r, 0.166666672f, hf);
    hh = hh - floorf(hh);
    float h6 = hh * 6.0f;
    float kr = 5.0f + h6; kr = (kr >= 6.0f) ? kr - 6.0f : kr;
    float kg = 3.0f + h6; kg = (kg >= 6.0f) ? kg - 6.0f : kg;
    float kb = 1.0f + h6; kb = (kb >= 6.0f) ? kb - 6.0f : kb;
    float wr = __saturatef(fminf(kr, 4.0f - kr));
    float wg = __saturatef(fminf(kg, 4.0f - kg));
    float wb = __saturatef(fminf(kb, 4.0f - kb));
    ro = fmaf(-wr, cr, maxc);
    go = fmaf(-wg, cr, maxc);
    bo = fmaf(-wb, cr, maxc);
}

__device__ __forceinline__ void do_triplet(const float4* __restrict__ px,
                                           float4* __restrict__ pox, int idx,
                                           float bf, float cf, float cmean,
                                           float sf, float hf)
{
    float4 R  = px[idx];
    float4 G  = px[idx + HW4];
    float4 Bv = px[idx + 2 * HW4];
    float4 Ro, Go, Bo;
    px_proc(R.x, G.x, Bv.x, bf, cf, cmean, sf, hf, Ro.x, Go.x, Bo.x);
    px_proc(R.y, G.y, Bv.y, bf, cf, cmean, sf, hf, Ro.y, Go.y, Bo.y);
    px_proc(R.z, G.z, Bv.z, bf, cf, cmean, sf, hf, Ro.z, Go.z, Bo.z);
    px_proc(R.w, G.w, Bv.w, bf, cf, cmean, sf, hf, Ro.w, Go.w, Bo.w);
    pox[idx]           = Ro;
    pox[idx + HW4]     = Go;
    pox[idx + 2 * HW4] = Bo;
}

__global__ void __launch_bounds__(256)
cr_main_kernel(const float* __restrict__ x,
               const float* __restrict__ bf_arr,
               const float* __restrict__ cf_arr,
               const float* __restrict__ sf_arr,
               const float* __restrict__ hf_arr,
               float* __restrict__ out)
{
    int b = blockIdx.x / BLKS_PER_BATCH;           // uniform per block
    int base4 = (blockIdx.x % BLKS_PER_BATCH) * 512 + threadIdx.x;

    __shared__ float sm[5];
    if (threadIdx.x < 32) {
        float v = 0.0f;
        for (int i = threadIdx.x; i < NBLK; i += 32) v += g_partial[b * NBLK + i];
        #pragma unroll
        for (int off = 16; off > 0; off >>= 1)
            v += __shfl_down_sync(0xFFFFFFFFu, v, off);
        if (threadIdx.x == 0) {
            float mean = v * (1.0f / (float)HW);
            float cf = cf_arr[b];
            sm[0] = (1.0f - cf) * mean;   // cmean
            sm[1] = bf_arr[b];
            sm[2] = cf;
            sm[3] = sf_arr[b];
            sm[4] = hf_arr[b];
        }
    }
    __syncthreads();
    float cmean = sm[0], bf = sm[1], cf = sm[2], sf = sm[3], hf = sm[4];

    size_t base = (size_t)b * 3 * HW;
    const float4* px  = (const float4*)(x + base);
    float4*       pox = (float4*)(out + base);

    // two independent float4 triplets per thread (6 loads in flight)
    do_triplet(px, pox, base4,       bf, cf, cmean, sf, hf);
    do_triplet(px, pox, base4 + 256, bf, cf, cmean, sf, hf);
}

extern "C" void kernel_launch(void* const* d_in, const int* in_sizes, int n_in,
                              void* d_out, int out_size)
{
    const float* x  = (const float*)d_in[0];
    const float* bf = (const float*)d_in[1];
    const float* cf = (const float*)d_in[2];
    const float* sf = (const float*)d_in[3];
    const float* hf = (const float*)d_in[4];
    float* out = (float*)d_out;

    cr_reduce_kernel<<<BATCH * NBLK, 256>>>(x, bf);
    cr_main_kernel<<<BATCH * BLKS_PER_BATCH, 256>>>(x, bf, cf, sf, hf, out);
}

// round 14
// speedup vs baseline: 1.2833x; 1.0360x over previous
#include <cuda_runtime.h>

#define BATCH 32
#define HW 307200            // 480*640
#define HW4 (HW/4)           // 76800 float4 per channel per batch
#define NBLK 75              // reduction blocks per batch -> 2400 total
#define CHUNK4 1024          // 76800/75 ; 4 iters/thread exactly
#define BLKS_PER_BATCH 150   // HW4 / (256*2) : 2 float4 triplets per thread

__device__ float g_partial[BATCH * NBLK];

// ---------------- Pass 1: per-batch gray sum of clip(x*bf) ----------------
// __ldcs on this pure-read stream measured 21.8us (R8); plain loads measured ~26us (R12).
__global__ void __launch_bounds__(256)
cr_reduce_kernel(const float* __restrict__ x, const float* __restrict__ bf_arr)
{
    int blk = blockIdx.x;          // 0 .. BATCH*NBLK-1
    int b   = blk / NBLK;
    int sub = blk % NBLK;
    float bf = bf_arr[b];

    const float4* base = (const float4*)(x + (size_t)b * 3 * HW);
    int start4 = sub * CHUNK4 + threadIdx.x;

    float acc = 0.0f;
    #pragma unroll
    for (int it = 0; it < 4; it++) {
        int p4 = start4 + it * 256;
        float4 r  = __ldcs(&base[p4]);
        float4 g  = __ldcs(&base[p4 + HW4]);
        float4 bl = __ldcs(&base[p4 + 2 * HW4]);
        float rr = __saturatef(r.x * bf) + __saturatef(r.y * bf)
                 + __saturatef(r.z * bf) + __saturatef(r.w * bf);
        float gg = __saturatef(g.x * bf) + __saturatef(g.y * bf)
                 + __saturatef(g.z * bf) + __saturatef(g.w * bf);
        float bb = __saturatef(bl.x * bf) + __saturatef(bl.y * bf)
                 + __saturatef(bl.z * bf) + __saturatef(bl.w * bf);
        acc += 0.299f * rr + 0.587f * gg + 0.114f * bb;
    }

    // warp reduce
    #pragma unroll
    for (int off = 16; off > 0; off >>= 1)
        acc += __shfl_down_sync(0xFFFFFFFFu, acc, off);

    __shared__ float s[8];
    int lane = threadIdx.x & 31, wid = threadIdx.x >> 5;
    if (lane == 0) s[wid] = acc;
    __syncthreads();
    if (wid == 0) {
        float v = (lane < 8) ? s[lane] : 0.0f;
        #pragma unroll
        for (int off = 4; off > 0; off >>= 1)
            v += __shfl_down_sync(0xFFFFFFFFu, v, off);
        if (lane == 0) g_partial[blk] = v;
    }
}

// ---------------- Pass 2: fused brightness/contrast/saturation/hue ----------------
// Branchless hue: out_n = v - cr * sat(min(k, 4-k)), k = (n + 6h) mod 6, n={5,3,1}.
__device__ __forceinline__ void px_proc(float r, float g, float bl,
                                        float bf, float cf, float cmean,
                                        float sf, float hf,
                                        float& ro, float& go, float& bo)
{
    r  = __saturatef(r * bf);
    g  = __saturatef(g * bf);
    bl = __saturatef(bl * bf);
    r  = __saturatef(fmaf(cf, r,  cmean));
    g  = __saturatef(fmaf(cf, g,  cmean));
    bl = __saturatef(fmaf(cf, bl, cmean));
    float gray = 0.299f * r + 0.587f * g + 0.114f * bl;
    float gm = (1.0f - sf) * gray;
    r  = __saturatef(fmaf(sf, r,  gm));
    g  = __saturatef(fmaf(sf, g,  gm));
    bl = __saturatef(fmaf(sf, bl, gm));
    float maxc = fmaxf(r, fmaxf(g, bl));
    float minc = fminf(r, fminf(g, bl));
    float cr = maxc - minc;
    float crd = (cr == 0.0f) ? 1.0f : cr;
    float inv = __fdividef(1.0f, crd);
    float num, off;
    if (maxc == r)      { num = g - bl;  off = 0.0f; }
    else if (maxc == g) { num = bl - r;  off = 2.0f; }
    else                { num = r - g;   off = 4.0f; }
    float h6r = fmaf(num, inv, off);
    float hh = fmaf(h6r, 0.166666672f, hf);
    hh = hh - floorf(hh);
    float h6 = hh * 6.0f;
    float kr = 5.0f + h6; kr = (kr >= 6.0f) ? kr - 6.0f : kr;
    float kg = 3.0f + h6; kg = (kg >= 6.0f) ? kg - 6.0f : kg;
    float kb = 1.0f + h6; kb = (kb >= 6.0f) ? kb - 6.0f : kb;
    float wr = __saturatef(fminf(kr, 4.0f - kr));
    float wg = __saturatef(fminf(kg, 4.0f - kg));
    float wb = __saturatef(fminf(kb, 4.0f - kb));
    ro = fmaf(-wr, cr, maxc);
    go = fmaf(-wg, cr, maxc);
    bo = fmaf(-wb, cr, maxc);
}

__device__ __forceinline__ void do_triplet(const float4* __restrict__ px,
                                           float4* __restrict__ pox, int idx,
                                           float bf, float cf, float cmean,
                                           float sf, float hf)
{
    float4 R  = px[idx];
    float4 G  = px[idx + HW4];
    float4 Bv = px[idx + 2 * HW4];
    float4 Ro, Go, Bo;
    px_proc(R.x, G.x, Bv.x, bf, cf, cmean, sf, hf, Ro.x, Go.x, Bo.x);
    px_proc(R.y, G.y, Bv.y, bf, cf, cmean, sf, hf, Ro.y, Go.y, Bo.y);
    px_proc(R.z, G.z, Bv.z, bf, cf, cmean, sf, hf, Ro.z, Go.z, Bo.z);
    px_proc(R.w, G.w, Bv.w, bf, cf, cmean, sf, hf, Ro.w, Go.w, Bo.w);
    pox[idx]           = Ro;
    pox[idx + HW4]     = Go;
    pox[idx + 2 * HW4] = Bo;
}

__global__ void __launch_bounds__(256)
cr_main_kernel(const float* __restrict__ x,
               const float* __restrict__ bf_arr,
               const float* __restrict__ cf_arr,
               const float* __restrict__ sf_arr,
               const float* __restrict__ hf_arr,
               float* __restrict__ out)
{
    int b = blockIdx.x / BLKS_PER_BATCH;           // uniform per block
    int base4 = (blockIdx.x % BLKS_PER_BATCH) * 512 + threadIdx.x;

    __shared__ float sm[5];
    if (threadIdx.x < 32) {
        float v = 0.0f;
        for (int i = threadIdx.x; i < NBLK; i += 32) v += g_partial[b * NBLK + i];
        #pragma unroll
        for (int off = 16; off > 0; off >>= 1)
            v += __shfl_down_sync(0xFFFFFFFFu, v, off);
        if (threadIdx.x == 0) {
            float mean = v * (1.0f / (float)HW);
            float cf = cf_arr[b];
            sm[0] = (1.0f - cf) * mean;   // cmean
            sm[1] = bf_arr[b];
            sm[2] = cf;
            sm[3] = sf_arr[b];
            sm[4] = hf_arr[b];
        }
    }
    __syncthreads();
    float cmean = sm[0], bf = sm[1], cf = sm[2], sf = sm[3], hf = sm[4];

    size_t base = (size_t)b * 3 * HW;
    const float4* px  = (const float4*)(x + base);
    float4*       pox = (float4*)(out + base);

    // two independent float4 triplets per thread (6 loads in flight)
    do_triplet(px, pox, base4,       bf, cf, cmean, sf, hf);
    do_triplet(px, pox, base4 + 256, bf, cf, cmean, sf, hf);
}

extern "C" void kernel_launch(void* const* d_in, const int* in_sizes, int n_in,
                              void* d_out, int out_size)
{
    const float* x  = (const float*)d_in[0];
    const float* bf = (const float*)d_in[1];
    const float* cf = (const float*)d_in[2];
    const float* sf = (const float*)d_in[3];
    const float* hf = (const float*)d_in[4];
    float* out = (float*)d_out;

    cr_reduce_kernel<<<BATCH * NBLK, 256>>>(x, bf);
    cr_main_kernel<<<BATCH * BLKS_PER_BATCH, 256>>>(x, bf, cf, sf, hf, out);
}

// round 15
// speedup vs baseline: 1.3021x; 1.0146x over previous
#include <cuda_runtime.h>

#define BATCH 32
#define HW 307200            // 480*640
#define HW4 (HW/4)           // 76800 float4 per channel per batch
#define NBLK 75              // reduction blocks per batch -> 2400 total
#define CHUNK4 1024          // 76800/75 ; 4 iters/thread exactly
#define BLKS_PER_BATCH 150   // HW4 / (256*2) : 2 float4 triplets per thread

__device__ float g_partial[BATCH * NBLK];

// ---------------- Pass 1: per-batch gray sum of clip(x*bf) ----------------
// __ldcs on this pure-read stream measured 21.8us (R8); plain loads ~26us (R12).
__global__ void __launch_bounds__(256)
cr_reduce_kernel(const float* __restrict__ x, const float* __restrict__ bf_arr)
{
    int blk = blockIdx.x;          // 0 .. BATCH*NBLK-1
    int b   = blk / NBLK;
    int sub = blk % NBLK;
    float bf = bf_arr[b];

    const float4* base = (const float4*)(x + (size_t)b * 3 * HW);
    int start4 = sub * CHUNK4 + threadIdx.x;

    float acc = 0.0f;
    #pragma unroll
    for (int it = 0; it < 4; it++) {
        int p4 = start4 + it * 256;
        float4 r  = __ldcs(&base[p4]);
        float4 g  = __ldcs(&base[p4 + HW4]);
        float4 bl = __ldcs(&base[p4 + 2 * HW4]);
        float rr = __saturatef(r.x * bf) + __saturatef(r.y * bf)
                 + __saturatef(r.z * bf) + __saturatef(r.w * bf);
        float gg = __saturatef(g.x * bf) + __saturatef(g.y * bf)
                 + __saturatef(g.z * bf) + __saturatef(g.w * bf);
        float bb = __saturatef(bl.x * bf) + __saturatef(bl.y * bf)
                 + __saturatef(bl.z * bf) + __saturatef(bl.w * bf);
        acc += 0.299f * rr + 0.587f * gg + 0.114f * bb;
    }

    // warp reduce
    #pragma unroll
    for (int off = 16; off > 0; off >>= 1)
        acc += __shfl_down_sync(0xFFFFFFFFu, acc, off);

    __shared__ float s[8];
    int lane = threadIdx.x & 31, wid = threadIdx.x >> 5;
    if (lane == 0) s[wid] = acc;
    __syncthreads();
    if (wid == 0) {
        float v = (lane < 8) ? s[lane] : 0.0f;
        #pragma unroll
        for (int off = 4; off > 0; off >>= 1)
            v += __shfl_down_sync(0xFFFFFFFFu, v, off);
        if (lane == 0) g_partial[blk] = v;
    }
}

// ---------------- Pass 2: fused brightness/contrast/saturation/hue ----------------
// Branchless hue: out_n = v - cr * sat(min(k, 4-k)), k = (n + 6h) mod 6, n={5,3,1}.
__device__ __forceinline__ void px_proc(float r, float g, float bl,
                                        float bf, float cf, float cmean,
                                        float sf, float hf,
                                        float& ro, float& go, float& bo)
{
    r  = __saturatef(r * bf);
    g  = __saturatef(g * bf);
    bl = __saturatef(bl * bf);
    r  = __saturatef(fmaf(cf, r,  cmean));
    g  = __saturatef(fmaf(cf, g,  cmean));
    bl = __saturatef(fmaf(cf, bl, cmean));
    float gray = 0.299f * r + 0.587f * g + 0.114f * bl;
    float gm = (1.0f - sf) * gray;
    r  = __saturatef(fmaf(sf, r,  gm));
    g  = __saturatef(fmaf(sf, g,  gm));
    bl = __saturatef(fmaf(sf, bl, gm));
    float maxc = fmaxf(r, fmaxf(g, bl));
    float minc = fminf(r, fminf(g, bl));
    float cr = maxc - minc;
    float crd = (cr == 0.0f) ? 1.0f : cr;
    float inv = __fdividef(1.0f, crd);
    float num, off;
    if (maxc == r)      { num = g - bl;  off = 0.0f; }
    else if (maxc == g) { num = bl - r;  off = 2.0f; }
    else                { num = r - g;   off = 4.0f; }
    float h6r = fmaf(num, inv, off);
    float hh = fmaf(h6r, 0.166666672f, hf);
    hh = hh - floorf(hh);
    float h6 = hh * 6.0f;
    float kr = 5.0f + h6; kr = (kr >= 6.0f) ? kr - 6.0f : kr;
    float kg = 3.0f + h6; kg = (kg >= 6.0f) ? kg - 6.0f : kg;
    float kb = 1.0f + h6; kb = (kb >= 6.0f) ? kb - 6.0f : kb;
    float wr = __saturatef(fminf(kr, 4.0f - kr));
    float wg = __saturatef(fminf(kg, 4.0f - kg));
    float wb = __saturatef(fminf(kb, 4.0f - kb));
    ro = fmaf(-wr, cr, maxc);
    go = fmaf(-wg, cr, maxc);
    bo = fmaf(-wb, cr, maxc);
}

__device__ __forceinline__ void do_triplet(const float4* __restrict__ px,
                                           float4* __restrict__ pox, int idx,
                                           float bf, float cf, float cmean,
                                           float sf, float hf)
{
    float4 R  = px[idx];
    float4 G  = px[idx + HW4];
    float4 Bv = px[idx + 2 * HW4];
    float4 Ro, Go, Bo;
    px_proc(R.x, G.x, Bv.x, bf, cf, cmean, sf, hf, Ro.x, Go.x, Bo.x);
    px_proc(R.y, G.y, Bv.y, bf, cf, cmean, sf, hf, Ro.y, Go.y, Bo.y);
    px_proc(R.z, G.z, Bv.z, bf, cf, cmean, sf, hf, Ro.z, Go.z, Bo.z);
    px_proc(R.w, G.w, Bv.w, bf, cf, cmean, sf, hf, Ro.w, Go.w, Bo.w);
    // evict-first stores: output is never re-read; keep L2 for the read stream
    __stcs(&pox[idx],           Ro);
    __stcs(&pox[idx + HW4],     Go);
    __stcs(&pox[idx + 2 * HW4], Bo);
}

__global__ void __launch_bounds__(256)
cr_main_kernel(const float* __restrict__ x,
               const float* __restrict__ bf_arr,
               const float* __restrict__ cf_arr,
               const float* __restrict__ sf_arr,
               const float* __restrict__ hf_arr,
               float* __restrict__ out)
{
    int b = blockIdx.x / BLKS_PER_BATCH;           // uniform per block
    int base4 = (blockIdx.x % BLKS_PER_BATCH) * 512 + threadIdx.x;

    __shared__ float sm[5];
    if (threadIdx.x < 32) {
        float v = 0.0f;
        for (int i = threadIdx.x; i < NBLK; i += 32) v += g_partial[b * NBLK + i];
        #pragma unroll
        for (int off = 16; off > 0; off >>= 1)
            v += __shfl_down_sync(0xFFFFFFFFu, v, off);
        if (threadIdx.x == 0) {
            float mean = v * (1.0f / (float)HW);
            float cf = cf_arr[b];
            sm[0] = (1.0f - cf) * mean;   // cmean
            sm[1] = bf_arr[b];
            sm[2] = cf;
            sm[3] = sf_arr[b];
            sm[4] = hf_arr[b];
        }
    }
    __syncthreads();
    float cmean = sm[0], bf = sm[1], cf = sm[2], sf = sm[3], hf = sm[4];

    size_t base = (size_t)b * 3 * HW;
    const float4* px  = (const float4*)(x + base);
    float4*       pox = (float4*)(out + base);

    // two independent float4 triplets per thread (6 loads in flight)
    do_triplet(px, pox, base4,       bf, cf, cmean, sf, hf);
    do_triplet(px, pox, base4 + 256, bf, cf, cmean, sf, hf);
}

extern "C" void kernel_launch(void* const* d_in, const int* in_sizes, int n_in,
                              void* d_out, int out_size)
{
    const float* x  = (const float*)d_in[0];
    const float* bf = (const float*)d_in[1];
    const float* cf = (const float*)d_in[2];
    const float* sf = (const float*)d_in[3];
    const float* hf = (const float*)d_in[4];
    float* out = (float*)d_out;

    cr_reduce_kernel<<<BATCH * NBLK, 256>>>(x, bf);
    cr_main_kernel<<<BATCH * BLKS_PER_BATCH, 256>>>(x, bf, cf, sf, hf, out);
}